// round 10
// baseline (speedup 1.0000x reference)
#include <cuda_runtime.h>
#include <cuda_fp16.h>
#include <cstdint>

// ---------------------------------------------------------------------------
// B=32, T=4096, K=1024 (2H), N=512 (DFF)
// HMMA GEMM, 2 CTAs/SM, 128 threads: warp tile M64 x N64, 2 N-passes of 256.
// R10: KCH=64 (half the barriers), 2-stage A/B smem rings, 128-B k-rows.
// ---------------------------------------------------------------------------
#define BATCH   32
#define TSEQ    4096
#define KDIM    1024
#define NDFF    512
#define MTILE   64
#define KCH     64
#define NCHUNKS 16
#define NTILES  (TSEQ / MTILE)     // 64
#define NCTAS   (BATCH * NTILES)   // 2048

__device__ __align__(128) __half g_Uh[NDFF * KDIM];             // 1 MB fp16 U [f][e]
__device__ __align__(128) float  g_ws[BATCH * NDFF];
__device__ __align__(128) float  g_partial[NCTAS * KDIM];       // 8 MB
__device__ int g_cnt[BATCH];

// Shared layout (bytes)
#define SM_WS   0                       // 512 f
#define SM_V    2048                    // 512 f
#define SM_EN   4096                    // 4*64 f
#define SM_ENF  5120                    // 64 f
#define SM_FLAG 5376                    // int
#define SM_A    8192                    // 2 stages x 8192
#define SM_B    24576                   // 2 stages x 32768
#define SMEM_TOTAL 90112

__device__ __forceinline__ uint32_t smem_u32(const void* p) {
    uint32_t a;
    asm("{ .reg .u64 t; cvta.to.shared.u64 t, %1; cvt.u32.u64 %0, t; }"
        : "=r"(a) : "l"(p));
    return a;
}
__device__ __forceinline__ void cp_async16(uint32_t dst, const void* src) {
    asm volatile("cp.async.cg.shared.global [%0], [%1], 16;"
                 :: "r"(dst), "l"(src) : "memory");
}
#define CP_COMMIT() asm volatile("cp.async.commit_group;" ::: "memory")
#define CP_WAIT0()  asm volatile("cp.async.wait_group 0;" ::: "memory")

__device__ __forceinline__ void ldsm4(uint32_t* r4, uint32_t addr) {
    asm volatile("ldmatrix.sync.aligned.m8n8.x4.shared.b16 {%0,%1,%2,%3}, [%4];"
                 : "=r"(r4[0]), "=r"(r4[1]), "=r"(r4[2]), "=r"(r4[3]) : "r"(addr));
}
__device__ __forceinline__ void mma16816(float* c, const uint32_t* a,
                                         uint32_t b0, uint32_t b1) {
    asm volatile(
        "mma.sync.aligned.m16n8k16.row.col.f32.f16.f16.f32 "
        "{%0,%1,%2,%3}, {%4,%5,%6,%7}, {%8,%9}, {%0,%1,%2,%3};"
        : "+f"(c[0]), "+f"(c[1]), "+f"(c[2]), "+f"(c[3])
        : "r"(a[0]), "r"(a[1]), "r"(a[2]), "r"(a[3]), "r"(b0), "r"(b1));
}
__device__ __forceinline__ uint4 cvt8(const float4& x, const float4& y) {
    uint4 u; __half2 t;
    t = __floats2half2_rn(x.x, x.y); u.x = *(uint32_t*)&t;
    t = __floats2half2_rn(x.z, x.w); u.y = *(uint32_t*)&t;
    t = __floats2half2_rn(y.x, y.y); u.z = *(uint32_t*)&t;
    t = __floats2half2_rn(y.z, y.w); u.w = *(uint32_t*)&t;
    return u;
}

// ---------------------------------------------------------------------------
// Fused prep: blocks 0..511 convU, 512..575 ws, 576 zero counters
// ---------------------------------------------------------------------------
__global__ void k_prep(const float* __restrict__ Uw, const float* __restrict__ s,
                       const float* __restrict__ W,  const float* __restrict__ Wb,
                       const float* __restrict__ Ub) {
    int blk = blockIdx.x;
    int tid = threadIdx.x;
    if (blk < 512) {
        int i = blk * 256 + tid;
        float4 v = reinterpret_cast<const float4*>(Uw)[i];
        __half2 p0 = __floats2half2_rn(v.x, v.y);
        __half2 p1 = __floats2half2_rn(v.z, v.w);
        uint2 u;
        u.x = *reinterpret_cast<uint32_t*>(&p0);
        u.y = *reinterpret_cast<uint32_t*>(&p1);
        *reinterpret_cast<uint2*>(&g_Uh[i * 4]) = u;
    } else if (blk < 576) {
        __shared__ float ssh[512];
        int q = blk - 512;
        int b = q >> 1;
        int f = ((q & 1) << 8) + tid;
        ssh[tid]       = s[b * 512 + tid];
        ssh[tid + 256] = s[b * 512 + tid + 256];
        __syncthreads();
        float acc = Wb[f] + Ub[f];
        const float4* Wr = reinterpret_cast<const float4*>(W + (size_t)f * 512);
#pragma unroll 4
        for (int e4 = 0; e4 < 128; e4++) {
            float4 w = Wr[e4];
            acc = fmaf(ssh[e4 * 4 + 0], w.x, acc);
            acc = fmaf(ssh[e4 * 4 + 1], w.y, acc);
            acc = fmaf(ssh[e4 * 4 + 2], w.z, acc);
            acc = fmaf(ssh[e4 * 4 + 3], w.w, acc);
        }
        g_ws[b * 512 + f] = acc;
    } else {
        if (tid < BATCH) g_cnt[tid] = 0;
    }
}

// ---------------------------------------------------------------------------
// Main kernel: 128 threads, 4 warps, warp tile M64 x N64, 2 CTAs/SM.
// Plain 128-B k-rows (KCH=64 fp16 = one SW128 atom row), SW128-swizzled.
// ---------------------------------------------------------------------------
__global__ __launch_bounds__(128, 2)
void k_main(const float* __restrict__ h, const float* __restrict__ V,
            const float* __restrict__ Vb, float* __restrict__ out) {
    extern __shared__ char smem[];
    const uint32_t sb = smem_u32(smem);
    const int tid  = threadIdx.x;
    const int wid  = tid >> 5;     // = ng, 0..3
    const int lane = tid & 31;
    const int b    = blockIdx.x >> 6;

    float* ws_s  = reinterpret_cast<float*>(smem + SM_WS);
    float* V_s   = reinterpret_cast<float*>(smem + SM_V);
    float* en_s  = reinterpret_cast<float*>(smem + SM_EN);
    float* enf_s = reinterpret_cast<float*>(smem + SM_ENF);
    int*   flag  = reinterpret_cast<int*>(smem + SM_FLAG);

    for (int i = tid; i < NDFF; i += 128) {
        ws_s[i] = g_ws[b * NDFF + i];
        V_s[i]  = V[i];
    }
    for (int i = tid; i < 4 * MTILE; i += 128) en_s[i] = 0.f;

    const float* hB = h + (size_t)blockIdx.x * (MTILE * KDIM);

    // ---- A stream map: thread -> (row am = tid>>1, half ah = tid&1) ----
    const int am = tid >> 1, ah = tid & 1;
    const uint32_t a_sts0 = (uint32_t)(am * 128 + ((ah * 64) ^ ((am & 7) * 16)));
    const float4* ap = reinterpret_cast<const float4*>(hB) + am * 256 + ah * 8;

    // ---- B cp.async map: 16 x 16B per thread per chunk ----
    const int bf_ = tid >> 3, bu = tid & 7;
    const uint32_t bdst0 = (uint32_t)(bf_ * 128 + ((bu * 16) ^ ((bf_ & 7) * 16)));
    const uint32_t bsrc0 = (uint32_t)(bf_ * KDIM + bu * 8);   // halves

    // ---- ldsm bases ----
    const int r = lane & 7;
    const int selA = (lane >> 3) & 1, selK = (lane >> 4) & 1;
    const int row0 = selA * 8 + r;
    const uint32_t abase0 = (uint32_t)(row0 * 128 +
                                       ((selK * 16) ^ ((row0 & 7) * 16)));
    const int selKb = (lane >> 3) & 1, selNb = (lane >> 4) & 1;
    const int f0 = selNb * 8 + r;
    const uint32_t bbase0 = (uint32_t)((wid * 64 + f0) * 128 +
                                       ((selKb * 16) ^ ((f0 & 7) * 16)));

    float4 p[8];   // A fp32 staging (one chunk)

    // ======================= two N-passes of 256 =======================
#pragma unroll 1
    for (int np = 0; np < 2; np++) {
        const __half* Ub2 = g_Uh + (size_t)(np * 256) * KDIM;

        float acc[4][8][4];
#pragma unroll
        for (int mi = 0; mi < 4; mi++)
#pragma unroll
            for (int ni = 0; ni < 8; ni++)
#pragma unroll
                for (int q = 0; q < 4; q++) acc[mi][ni][q] = 0.f;

        __syncthreads();   // stage reuse across passes

        // ---- prologue: B(0) cp.async; A(0) LDG/cvt/STS; A(1) LDG ----
        {
            uint32_t dst = sb + SM_B + bdst0;
            const __half* src = Ub2 + bsrc0;
#pragma unroll
            for (int it = 0; it < 16; it++)
                cp_async16(dst + it * 2048, src + it * (16 * KDIM));
            CP_COMMIT();
#pragma unroll
            for (int j = 0; j < 8; j++) p[j] = ap[j];
#pragma unroll
            for (int u = 0; u < 4; u++)
                *reinterpret_cast<uint4*>(smem + SM_A + (a_sts0 ^ (u << 4)))
                    = cvt8(p[2 * u], p[2 * u + 1]);
#pragma unroll
            for (int j = 0; j < 8; j++) p[j] = ap[16 + j];
            CP_WAIT0();
            __syncthreads();
        }

        // ---------------- K mainloop ----------------
#pragma unroll 1
        for (int c = 0; c < NCHUNKS; c++) {
            const uint32_t ab = sb + SM_A + (uint32_t)(c & 1) * 8192;
            const uint32_t bb = sb + SM_B + (uint32_t)(c & 1) * 32768;

            // fragment prologue: A[ki=0] x4, B[g=0]
            uint32_t af[2][4][4];
            uint32_t bfr[2][4];
#pragma unroll
            for (int mi = 0; mi < 4; mi++)
                ldsm4(af[0][mi], ab + abase0 + mi * 2048);
            ldsm4(bfr[0], bb + bbase0);

            // future-chunk memory ops (issued under ldsm latency)
            if (c + 1 < NCHUNKS) {
                char* an = smem + SM_A + ((c + 1) & 1) * 8192;
#pragma unroll
                for (int u = 0; u < 4; u++)
                    *reinterpret_cast<uint4*>(an + (a_sts0 ^ (u << 4)))
                        = cvt8(p[2 * u], p[2 * u + 1]);
                uint32_t dst = sb + SM_B + ((c + 1) & 1) * 32768 + bdst0;
                const __half* src = Ub2 + bsrc0 + (c + 1) * KCH;
#pragma unroll
                for (int it = 0; it < 16; it++)
                    cp_async16(dst + it * 2048, src + it * (16 * KDIM));
                if (c + 2 < NCHUNKS) {
#pragma unroll
                    for (int j = 0; j < 8; j++) p[j] = ap[(c + 2) * 16 + j];
                }
            }
            CP_COMMIT();

            // g = ki*4 + nj stream, 16 groups, 1-ahead B ring
#pragma unroll
            for (int g = 0; g < 16; g++) {
                const int ki = g >> 2, nj = g & 3;
                if (g < 15) {
                    const int gk = (g + 1) >> 2, gn = (g + 1) & 3;
                    ldsm4(bfr[(g + 1) & 1],
                          bb + ((bbase0 + gn * 2048) ^ (uint32_t)(gk << 5)));
                }
                if (nj == 2 && ki < 3) {
#pragma unroll
                    for (int mi = 0; mi < 4; mi++)
                        ldsm4(af[(ki + 1) & 1][mi],
                              ab + ((abase0 + mi * 2048) ^ (uint32_t)((ki + 1) << 5)));
                }
#pragma unroll
                for (int mi = 0; mi < 4; mi++) {
                    mma16816(acc[mi][2 * nj],     af[ki & 1][mi],
                             bfr[g & 1][0], bfr[g & 1][1]);
                    mma16816(acc[mi][2 * nj + 1], af[ki & 1][mi],
                             bfr[g & 1][2], bfr[g & 1][3]);
                }
            }

            CP_WAIT0();
            __syncthreads();
        }

        // ---------------- epilogue: energy partials ----------------
#pragma unroll
        for (int mi = 0; mi < 4; mi++) {
#pragma unroll
            for (int rh = 0; rh < 2; rh++) {
                float s = 0.f;
#pragma unroll
                for (int nj = 0; nj < 4; nj++) {
#pragma unroll
                    for (int jj = 0; jj < 2; jj++) {
#pragma unroll
                        for (int q = 0; q < 2; q++) {
                            int f = np * 256 + wid * 64 + nj * 16 + jj * 8 +
                                    ((lane & 3) << 1) + q;
                            float z = ws_s[f] + acc[mi][nj * 2 + jj][rh * 2 + q];
                            z = fminf(fmaxf(z, -15.f), 15.f);
                            float e2 = __expf(2.f * z);
                            float x = __fdividef(e2 - 1.f, e2 + 1.f);
                            s = fmaf(V_s[f], x, s);
                        }
                    }
                }
                s += __shfl_xor_sync(0xffffffffu, s, 1);
                s += __shfl_xor_sync(0xffffffffu, s, 2);
                if ((lane & 3) == 0)
                    en_s[(wid << 6) + mi * 16 + rh * 8 + (lane >> 2)] += s;
            }
        }
    }

    // ---------------- finalize energy ----------------
    __syncthreads();
    if (tid < MTILE) {
        float e = Vb[0];
#pragma unroll
        for (int w = 0; w < 4; w++) e += en_s[(w << 6) + tid];
        enf_s[tid] = e;
    }
    __syncthreads();

    // ---------------- context partial: sum_m energy[m] * h[m, e] --------------
    {
        const float4* h4 = reinterpret_cast<const float4*>(hB);
        float4 a0 = make_float4(0.f, 0.f, 0.f, 0.f);
        float4 a1 = make_float4(0.f, 0.f, 0.f, 0.f);
#pragma unroll 8
        for (int m = 0; m < MTILE; m++) {
            float en = enf_s[m];
            float4 v0 = h4[m * 256 + tid * 2];
            float4 v1 = h4[m * 256 + tid * 2 + 1];
            a0.x = fmaf(en, v0.x, a0.x); a0.y = fmaf(en, v0.y, a0.y);
            a0.z = fmaf(en, v0.z, a0.z); a0.w = fmaf(en, v0.w, a0.w);
            a1.x = fmaf(en, v1.x, a1.x); a1.y = fmaf(en, v1.y, a1.y);
            a1.z = fmaf(en, v1.z, a1.z); a1.w = fmaf(en, v1.w, a1.w);
        }
        float4* gp = reinterpret_cast<float4*>(g_partial) +
                     ((size_t)blockIdx.x << 8);
        gp[tid * 2]     = a0;
        gp[tid * 2 + 1] = a1;
    }

    // ---------------- last CTA per batch reduces (deterministic order) --------
    __threadfence();
    if (tid == 0) {
        int old = atomicAdd(&g_cnt[b], 1);
        *flag = (old == NTILES - 1) ? 1 : 0;
    }
    __syncthreads();
    if (*flag) {
        __threadfence();
        const float4* gp = reinterpret_cast<const float4*>(
            g_partial + ((size_t)b * NTILES) * KDIM);
        float4 a0 = make_float4(0.f, 0.f, 0.f, 0.f);
        float4 a1 = make_float4(0.f, 0.f, 0.f, 0.f);
#pragma unroll 8
        for (int tt = 0; tt < NTILES; tt++) {
            float4 v0 = gp[tt * 256 + tid * 2];
            float4 v1 = gp[tt * 256 + tid * 2 + 1];
            a0.x += v0.x; a0.y += v0.y; a0.z += v0.z; a0.w += v0.w;
            a1.x += v1.x; a1.y += v1.y; a1.z += v1.z; a1.w += v1.w;
        }
        float4* o4 = reinterpret_cast<float4*>(out) + b * 256;
        o4[tid * 2]     = a0;
        o4[tid * 2 + 1] = a1;
    }
}

// ---------------------------------------------------------------------------
extern "C" void kernel_launch(void* const* d_in, const int* in_sizes, int n_in,
                              void* d_out, int out_size) {
    (void)in_sizes; (void)n_in; (void)out_size;
    const float* s  = (const float*)d_in[0];
    const float* h  = (const float*)d_in[1];
    const float* Ww = (const float*)d_in[2];
    const float* Wb = (const float*)d_in[3];
    const float* Uw = (const float*)d_in[4];
    const float* Ub = (const float*)d_in[5];
    const float* Vw = (const float*)d_in[6];
    const float* Vb = (const float*)d_in[7];
    float* out = (float*)d_out;

    cudaFuncSetAttribute(k_main, cudaFuncAttributeMaxDynamicSharedMemorySize,
                         SMEM_TOTAL);

    k_prep<<<577, 256>>>(Uw, s, Ww, Wb, Ub);
    k_main<<<NCTAS, 128, SMEM_TOTAL>>>(h, Vw, Vb, out);
}

// round 11
// speedup vs baseline: 1.3725x; 1.3725x over previous
#include <cuda_runtime.h>
#include <cuda_fp16.h>
#include <cstdint>

// ---------------------------------------------------------------------------
// B=32, T=4096, K=1024 (2H), N=512 (DFF)
// HMMA GEMM, 2 CTAs/SM, 128 threads: warp tile M64 x N64, 2 N-passes of 256.
// R11: KCH=64, 2-stage rings, in-chunk A staging (register-neutral).
// ---------------------------------------------------------------------------
#define BATCH   32
#define TSEQ    4096
#define KDIM    1024
#define NDFF    512
#define MTILE   64
#define KCH     64
#define NCHUNKS 16
#define NTILES  (TSEQ / MTILE)     // 64
#define NCTAS   (BATCH * NTILES)   // 2048

__device__ __align__(128) __half g_Uh[NDFF * KDIM];             // 1 MB fp16 U [f][e]
__device__ __align__(128) float  g_ws[BATCH * NDFF];
__device__ __align__(128) float  g_partial[NCTAS * KDIM];       // 8 MB
__device__ int g_cnt[BATCH];

// Shared layout (bytes)
#define SM_WS   0                       // 512 f
#define SM_V    2048                    // 512 f
#define SM_EN   4096                    // 4*64 f
#define SM_ENF  5120                    // 64 f
#define SM_FLAG 5376                    // int
#define SM_A    8192                    // 2 stages x 8192
#define SM_B    24576                   // 2 stages x 32768
#define SMEM_TOTAL 90112

__device__ __forceinline__ uint32_t smem_u32(const void* p) {
    uint32_t a;
    asm("{ .reg .u64 t; cvta.to.shared.u64 t, %1; cvt.u32.u64 %0, t; }"
        : "=r"(a) : "l"(p));
    return a;
}
__device__ __forceinline__ void cp_async16(uint32_t dst, const void* src) {
    asm volatile("cp.async.cg.shared.global [%0], [%1], 16;"
                 :: "r"(dst), "l"(src) : "memory");
}
#define CP_COMMIT() asm volatile("cp.async.commit_group;" ::: "memory")
#define CP_WAIT0()  asm volatile("cp.async.wait_group 0;" ::: "memory")

__device__ __forceinline__ void ldsm4(uint32_t* r4, uint32_t addr) {
    asm volatile("ldmatrix.sync.aligned.m8n8.x4.shared.b16 {%0,%1,%2,%3}, [%4];"
                 : "=r"(r4[0]), "=r"(r4[1]), "=r"(r4[2]), "=r"(r4[3]) : "r"(addr));
}
__device__ __forceinline__ void mma16816(float* c, const uint32_t* a,
                                         uint32_t b0, uint32_t b1) {
    asm volatile(
        "mma.sync.aligned.m16n8k16.row.col.f32.f16.f16.f32 "
        "{%0,%1,%2,%3}, {%4,%5,%6,%7}, {%8,%9}, {%0,%1,%2,%3};"
        : "+f"(c[0]), "+f"(c[1]), "+f"(c[2]), "+f"(c[3])
        : "r"(a[0]), "r"(a[1]), "r"(a[2]), "r"(a[3]), "r"(b0), "r"(b1));
}
__device__ __forceinline__ uint4 cvt8(const float4& x, const float4& y) {
    uint4 u; __half2 t;
    t = __floats2half2_rn(x.x, x.y); u.x = *(uint32_t*)&t;
    t = __floats2half2_rn(x.z, x.w); u.y = *(uint32_t*)&t;
    t = __floats2half2_rn(y.x, y.y); u.z = *(uint32_t*)&t;
    t = __floats2half2_rn(y.z, y.w); u.w = *(uint32_t*)&t;
    return u;
}

// ---------------------------------------------------------------------------
// Fused prep: blocks 0..511 convU, 512..575 ws, 576 zero counters
// ---------------------------------------------------------------------------
__global__ void k_prep(const float* __restrict__ Uw, const float* __restrict__ s,
                       const float* __restrict__ W,  const float* __restrict__ Wb,
                       const float* __restrict__ Ub) {
    int blk = blockIdx.x;
    int tid = threadIdx.x;
    if (blk < 512) {
        int i = blk * 256 + tid;
        float4 v = reinterpret_cast<const float4*>(Uw)[i];
        __half2 p0 = __floats2half2_rn(v.x, v.y);
        __half2 p1 = __floats2half2_rn(v.z, v.w);
        uint2 u;
        u.x = *reinterpret_cast<uint32_t*>(&p0);
        u.y = *reinterpret_cast<uint32_t*>(&p1);
        *reinterpret_cast<uint2*>(&g_Uh[i * 4]) = u;
    } else if (blk < 576) {
        __shared__ float ssh[512];
        int q = blk - 512;
        int b = q >> 1;
        int f = ((q & 1) << 8) + tid;
        ssh[tid]       = s[b * 512 + tid];
        ssh[tid + 256] = s[b * 512 + tid + 256];
        __syncthreads();
        float acc = Wb[f] + Ub[f];
        const float4* Wr = reinterpret_cast<const float4*>(W + (size_t)f * 512);
#pragma unroll 4
        for (int e4 = 0; e4 < 128; e4++) {
            float4 w = Wr[e4];
            acc = fmaf(ssh[e4 * 4 + 0], w.x, acc);
            acc = fmaf(ssh[e4 * 4 + 1], w.y, acc);
            acc = fmaf(ssh[e4 * 4 + 2], w.z, acc);
            acc = fmaf(ssh[e4 * 4 + 3], w.w, acc);
        }
        g_ws[b * 512 + f] = acc;
    } else {
        if (tid < BATCH) g_cnt[tid] = 0;
    }
}

// ---------------------------------------------------------------------------
// Main kernel: 128 threads, 4 warps, warp tile M64 x N64, 2 CTAs/SM.
// Standard SW128 layout: k-row m = smem row m (128 B), col ^= (row&7)*16.
// ---------------------------------------------------------------------------
__global__ __launch_bounds__(128, 2)
void k_main(const float* __restrict__ h, const float* __restrict__ V,
            const float* __restrict__ Vb, float* __restrict__ out) {
    extern __shared__ char smem[];
    const uint32_t sb = smem_u32(smem);
    const int tid  = threadIdx.x;
    const int wid  = tid >> 5;     // = ng, 0..3
    const int lane = tid & 31;
    const int b    = blockIdx.x >> 6;

    float* ws_s  = reinterpret_cast<float*>(smem + SM_WS);
    float* V_s   = reinterpret_cast<float*>(smem + SM_V);
    float* en_s  = reinterpret_cast<float*>(smem + SM_EN);
    float* enf_s = reinterpret_cast<float*>(smem + SM_ENF);
    int*   flag  = reinterpret_cast<int*>(smem + SM_FLAG);

    for (int i = tid; i < NDFF; i += 128) {
        ws_s[i] = g_ws[b * NDFF + i];
        V_s[i]  = V[i];
    }
    for (int i = tid; i < 4 * MTILE; i += 128) en_s[i] = 0.f;

    const float* hB = h + (size_t)blockIdx.x * (MTILE * KDIM);

    // ---- A map: thread -> (row0 = tid>>3, seg sg = tid&7); 4 rows (+16 each)
    const int arow = tid >> 3, sg = tid & 7;
    const uint32_t a_sts0 = (uint32_t)(arow * 128 + ((sg * 16) ^ ((arow & 7) * 16)));
    const float4* apg = reinterpret_cast<const float4*>(hB) + arow * 256 + sg * 2;

    // ---- B cp.async map: same (row,seg) decomposition; 16 rows (+16 each)
    const uint32_t bdst0 = a_sts0;
    const uint32_t bsrc0 = (uint32_t)(arow * KDIM + sg * 8);   // halves

    // ---- ldsm bases ----
    const int r = lane & 7;
    const int selA = (lane >> 3) & 1, selK = (lane >> 4) & 1;
    const int row0 = selA * 8 + r;
    const uint32_t abase0 = (uint32_t)(row0 * 128 +
                                       ((selK * 16) ^ ((row0 & 7) * 16)));
    const int selKb = (lane >> 3) & 1, selNb = (lane >> 4) & 1;
    const int f0 = selNb * 8 + r;
    const uint32_t bbase0 = (uint32_t)((wid * 64 + f0) * 128 +
                                       ((selKb * 16) ^ ((f0 & 7) * 16)));

    // ======================= two N-passes of 256 =======================
#pragma unroll 1
    for (int np = 0; np < 2; np++) {
        const __half* Ub2 = g_Uh + (size_t)(np * 256) * KDIM;

        float acc[4][8][4];
#pragma unroll
        for (int mi = 0; mi < 4; mi++)
#pragma unroll
            for (int ni = 0; ni < 8; ni++)
#pragma unroll
                for (int q = 0; q < 4; q++) acc[mi][ni][q] = 0.f;

        __syncthreads();   // stage ring reuse safe

        // ---- pass prologue: B(0) cp.async; A(0) LDG/cvt/STS ----
        {
            uint32_t dst = sb + SM_B + bdst0;
            const __half* src = Ub2 + bsrc0;
#pragma unroll
            for (int it = 0; it < 16; it++)
                cp_async16(dst + it * 2048, src + it * (16 * KDIM));
            CP_COMMIT();
#pragma unroll
            for (int u = 0; u < 4; u++) {
                float4 x = apg[u * 16 * 256];
                float4 y = apg[u * 16 * 256 + 1];
                *reinterpret_cast<uint4*>(smem + SM_A + a_sts0 + u * 2048)
                    = cvt8(x, y);
            }
            CP_WAIT0();
            __syncthreads();
        }

        // ---------------- K mainloop ----------------
#pragma unroll 1
        for (int c = 0; c < NCHUNKS; c++) {
            const uint32_t ab = sb + SM_A + (uint32_t)(c & 1) * 8192;
            const uint32_t bb = sb + SM_B + (uint32_t)(c & 1) * 32768;
            char* an = smem + SM_A + ((c + 1) & 1) * 8192;

            // fragment prologue: A[ki=0] x4, B[g=0]
            uint32_t af[2][4][4];
            uint32_t bfr[2][4];
#pragma unroll
            for (int mi = 0; mi < 4; mi++)
                ldsm4(af[0][mi], ab + abase0 + mi * 2048);
            ldsm4(bfr[0], bb + bbase0);

            // B(c+1) cp.async + A(c+1) LDG batch0, under ldsm latency
            float4 p0x, p0y, p1x, p1y;
            if (c + 1 < NCHUNKS) {
                uint32_t dst = sb + SM_B + ((c + 1) & 1) * 32768 + bdst0;
                const __half* src = Ub2 + bsrc0 + (c + 1) * KCH;
#pragma unroll
                for (int it = 0; it < 16; it++)
                    cp_async16(dst + it * 2048, src + it * (16 * KDIM));
                const float4* ap = apg + (c + 1) * 16;
                p0x = ap[0];            p0y = ap[1];
                p1x = ap[16 * 256];     p1y = ap[16 * 256 + 1];
            }
            CP_COMMIT();

            // g = ki*4 + nj stream, 16 groups, 1-ahead B ring
#pragma unroll
            for (int g = 0; g < 16; g++) {
                const int ki = g >> 2, nj = g & 3;
                if (g < 15) {
                    const int gk = (g + 1) >> 2, gn = (g + 1) & 3;
                    ldsm4(bfr[(g + 1) & 1],
                          bb + ((bbase0 + gn * 2048) ^ (uint32_t)(gk * 32)));
                }
                if (nj == 2 && ki < 3) {
#pragma unroll
                    for (int mi = 0; mi < 4; mi++)
                        ldsm4(af[(ki + 1) & 1][mi],
                              ab + ((abase0 + mi * 2048) ^ (uint32_t)((ki + 1) * 32)));
                }
                if (g == 4 && c + 1 < NCHUNKS) {
                    // cvt+STS batch0 (rows u=0,1), LDG batch1
                    *reinterpret_cast<uint4*>(an + a_sts0)        = cvt8(p0x, p0y);
                    *reinterpret_cast<uint4*>(an + a_sts0 + 2048) = cvt8(p1x, p1y);
                    const float4* ap = apg + (c + 1) * 16;
                    p0x = ap[32 * 256];     p0y = ap[32 * 256 + 1];
                    p1x = ap[48 * 256];     p1y = ap[48 * 256 + 1];
                }
                if (g == 12 && c + 1 < NCHUNKS) {
                    *reinterpret_cast<uint4*>(an + a_sts0 + 4096) = cvt8(p0x, p0y);
                    *reinterpret_cast<uint4*>(an + a_sts0 + 6144) = cvt8(p1x, p1y);
                }
#pragma unroll
                for (int mi = 0; mi < 4; mi++) {
                    mma16816(acc[mi][2 * nj],     af[ki & 1][mi],
                             bfr[g & 1][0], bfr[g & 1][1]);
                    mma16816(acc[mi][2 * nj + 1], af[ki & 1][mi],
                             bfr[g & 1][2], bfr[g & 1][3]);
                }
            }

            CP_WAIT0();
            __syncthreads();
        }

        // ---------------- epilogue: energy partials ----------------
#pragma unroll
        for (int mi = 0; mi < 4; mi++) {
#pragma unroll
            for (int rh = 0; rh < 2; rh++) {
                float s = 0.f;
#pragma unroll
                for (int nj = 0; nj < 4; nj++) {
#pragma unroll
                    for (int jj = 0; jj < 2; jj++) {
#pragma unroll
                        for (int q = 0; q < 2; q++) {
                            int f = np * 256 + wid * 64 + nj * 16 + jj * 8 +
                                    ((lane & 3) << 1) + q;
                            float z = ws_s[f] + acc[mi][nj * 2 + jj][rh * 2 + q];
                            z = fminf(fmaxf(z, -15.f), 15.f);
                            float e2 = __expf(2.f * z);
                            float x = __fdividef(e2 - 1.f, e2 + 1.f);
                            s = fmaf(V_s[f], x, s);
                        }
                    }
                }
                s += __shfl_xor_sync(0xffffffffu, s, 1);
                s += __shfl_xor_sync(0xffffffffu, s, 2);
                if ((lane & 3) == 0)
                    en_s[(wid << 6) + mi * 16 + rh * 8 + (lane >> 2)] += s;
            }
        }
    }

    // ---------------- finalize energy ----------------
    __syncthreads();
    if (tid < MTILE) {
        float e = Vb[0];
#pragma unroll
        for (int w = 0; w < 4; w++) e += en_s[(w << 6) + tid];
        enf_s[tid] = e;
    }
    __syncthreads();

    // ---------------- context partial: sum_m energy[m] * h[m, e] --------------
    {
        const float4* h4 = reinterpret_cast<const float4*>(hB);
        float4 a0 = make_float4(0.f, 0.f, 0.f, 0.f);
        float4 a1 = make_float4(0.f, 0.f, 0.f, 0.f);
#pragma unroll 8
        for (int m = 0; m < MTILE; m++) {
            float en = enf_s[m];
            float4 v0 = h4[m * 256 + tid * 2];
            float4 v1 = h4[m * 256 + tid * 2 + 1];
            a0.x = fmaf(en, v0.x, a0.x); a0.y = fmaf(en, v0.y, a0.y);
            a0.z = fmaf(en, v0.z, a0.z); a0.w = fmaf(en, v0.w, a0.w);
            a1.x = fmaf(en, v1.x, a1.x); a1.y = fmaf(en, v1.y, a1.y);
            a1.z = fmaf(en, v1.z, a1.z); a1.w = fmaf(en, v1.w, a1.w);
        }
        float4* gp = reinterpret_cast<float4*>(g_partial) +
                     ((size_t)blockIdx.x << 8);
        gp[tid * 2]     = a0;
        gp[tid * 2 + 1] = a1;
    }

    // ---------------- last CTA per batch reduces (deterministic order) --------
    __threadfence();
    if (tid == 0) {
        int old = atomicAdd(&g_cnt[b], 1);
        *flag = (old == NTILES - 1) ? 1 : 0;
    }
    __syncthreads();
    if (*flag) {
        __threadfence();
        const float4* gp = reinterpret_cast<const float4*>(
            g_partial + ((size_t)b * NTILES) * KDIM);
        float4 a0 = make_float4(0.f, 0.f, 0.f, 0.f);
        float4 a1 = make_float4(0.f, 0.f, 0.f, 0.f);
#pragma unroll 8
        for (int tt = 0; tt < NTILES; tt++) {
            float4 v0 = gp[tt * 256 + tid * 2];
            float4 v1 = gp[tt * 256 + tid * 2 + 1];
            a0.x += v0.x; a0.y += v0.y; a0.z += v0.z; a0.w += v0.w;
            a1.x += v1.x; a1.y += v1.y; a1.z += v1.z; a1.w += v1.w;
        }
        float4* o4 = reinterpret_cast<float4*>(out) + b * 256;
        o4[tid * 2]     = a0;
        o4[tid * 2 + 1] = a1;
    }
}

// ---------------------------------------------------------------------------
extern "C" void kernel_launch(void* const* d_in, const int* in_sizes, int n_in,
                              void* d_out, int out_size) {
    (void)in_sizes; (void)n_in; (void)out_size;
    const float* s  = (const float*)d_in[0];
    const float* h  = (const float*)d_in[1];
    const float* Ww = (const float*)d_in[2];
    const float* Wb = (const float*)d_in[3];
    const float* Uw = (const float*)d_in[4];
    const float* Ub = (const float*)d_in[5];
    const float* Vw = (const float*)d_in[6];
    const float* Vb = (const float*)d_in[7];
    float* out = (float*)d_out;

    cudaFuncSetAttribute(k_main, cudaFuncAttributeMaxDynamicSharedMemorySize,
                         SMEM_TOTAL);

    k_prep<<<577, 256>>>(Uw, s, Ww, Wb, Ub);
    k_main<<<NCTAS, 128, SMEM_TOTAL>>>(h, Vw, Vb, out);
}